// round 16
// baseline (speedup 1.0000x reference)
#include <cuda_runtime.h>
#include <math.h>
#include <stdint.h>

#define SEQ 1024
#define CH  64
#define BT  128
#define NTILES 8
#define NTH 288          // 8 consumer warps + 1 producer warp

// smem word offsets
#define QHI_W 0
#define QLO_W 4352
#define BUF_W 8704            // + buf*8704 : K hi (4352 words), V (+4352)
#define MB_W  26112           // mbarriers
#define SMEM_WORDS 26120
#define SMEM_BYTES (SMEM_WORDS * 4)   // 104480
#define OST 132

__device__ __forceinline__ void split2h(float f0, float f1, unsigned& hi, unsigned& lo) {
    unsigned h;
    asm("cvt.rn.f16x2.f32 %0, %1, %2;" : "=r"(h) : "f"(f1), "f"(f0));
    float h0, h1;
    asm("{ .reg .b16 a,b; mov.b32 {a,b}, %2; cvt.f32.f16 %0, a; cvt.f32.f16 %1, b; }"
        : "=f"(h0), "=f"(h1) : "r"(h));
    float r0 = f0 - h0, r1 = f1 - h1;
    asm("cvt.rn.f16x2.f32 %0, %1, %2;" : "=r"(lo) : "f"(r1), "f"(r0));
    hi = h;
}
__device__ __forceinline__ unsigned packh(float f0, float f1) {
    unsigned h;
    asm("cvt.rn.f16x2.f32 %0, %1, %2;" : "=r"(h) : "f"(f1), "f"(f0));
    return h;
}
__device__ __forceinline__ void mma_f16(float* d, const unsigned* a, const unsigned* b) {
    asm volatile(
        "mma.sync.aligned.m16n8k16.row.col.f32.f16.f16.f32 "
        "{%0,%1,%2,%3}, {%4,%5,%6,%7}, {%8,%9}, {%0,%1,%2,%3};\n"
        : "+f"(d[0]), "+f"(d[1]), "+f"(d[2]), "+f"(d[3])
        : "r"(a[0]), "r"(a[1]), "r"(a[2]), "r"(a[3]), "r"(b[0]), "r"(b[1]));
}
__device__ __forceinline__ uint32_t smem_u32(const void* p) {
    uint32_t a;
    asm("{ .reg .u64 t; cvta.to.shared.u64 t, %1; cvt.u32.u64 %0, t; }" : "=r"(a) : "l"(p));
    return a;
}
#define MBAR_INIT(mb, cnt) \
    asm volatile("mbarrier.init.shared.b64 [%0], %1;" :: "r"(mb), "r"((uint32_t)(cnt)) : "memory")
#define MBAR_ARRIVE(mb) \
    asm volatile("mbarrier.arrive.release.cta.shared::cta.b64 _, [%0];" :: "r"(mb) : "memory")
#define BAR_CONS() asm volatile("bar.sync 1, 256;" ::: "memory")

__device__ __forceinline__ void mbar_wait(uint32_t mb, uint32_t parity) {
    uint32_t done;
    asm volatile("{\n\t.reg .pred p;\n\t"
        "mbarrier.try_wait.parity.acquire.cta.shared::cta.b64 p, [%1], %2;\n\t"
        "selp.b32 %0, 1, 0, p;\n\t}" : "=r"(done) : "r"(mb), "r"(parity) : "memory");
    while (!done) {
        asm volatile("{\n\t.reg .pred p;\n\t"
            "mbarrier.try_wait.parity.acquire.cta.shared::cta.b64 p, [%1], %2;\n\t"
            "selp.b32 %0, 1, 0, p;\n\t}" : "=r"(done) : "r"(mb), "r"(parity) : "memory");
    }
}

// ============ single fused kernel: producer warp converts K/V in-flight ============
__global__ __launch_bounds__(NTH, 1)
void qkv_attn_v16(const float* __restrict__ qkv, float* __restrict__ out) {
    extern __shared__ unsigned smu[];
    float* smf = (float*)smu;

    const int t0 = blockIdx.x * BT;
    const int hb = blockIdx.y;
    const int b  = hb >> 4;
    const int h  = hb & 15;

    const float* qg = qkv + ((size_t)b * 3072 + (size_t)h * CH) * SEQ;
    const float* kg = qg + (size_t)1024 * SEQ;
    const float* vg = qg + (size_t)2048 * SEQ;
    float*       og = out + ((size_t)b * 1024 + (size_t)h * CH) * SEQ;

    const int tid  = threadIdx.x;
    const int wid  = tid >> 5;
    const int lane = tid & 31;
    const uint32_t smb = smem_u32(smu);

    const uint32_t FULL0  = smb + (MB_W + 0) * 4;
    const uint32_t FULL1  = smb + (MB_W + 2) * 4;
    const uint32_t EMPTY0 = smb + (MB_W + 4) * 4;
    const uint32_t EMPTY1 = smb + (MB_W + 6) * 4;

    if (tid == 0) {
        MBAR_INIT(FULL0, 32);   MBAR_INIT(FULL1, 32);
        MBAR_INIT(EMPTY0, 256); MBAR_INIT(EMPTY1, 256);
    }
    __syncthreads();

    if (wid == 8) {
        // ================= producer warp: LDG fp32 -> packh -> STS =================
#pragma unroll
        for (int st = 0; st < NTILES; st++) {
            const int buf = st & 1;
            const uint32_t EMPTY = buf ? EMPTY1 : EMPTY0;
            const uint32_t FULL  = buf ? FULL1  : FULL0;
            if (st >= 2) mbar_wait(EMPTY, (uint32_t)(((st >> 1) - 1) & 1));
            const int s0 = st * 128;
            const int KHIw = BUF_W + buf * 8704;
            const int VHIw = KHIw + 4352;

            // K: row j = channel-pair c2; lane covers s-words 4*lane..4*lane+3
#pragma unroll 4
            for (int j = 0; j < 32; j++) {
                const float4 a = *(const float4*)(kg + (size_t)(2 * j)     * SEQ + s0 + 4 * lane);
                const float4 c = *(const float4*)(kg + (size_t)(2 * j + 1) * SEQ + s0 + 4 * lane);
                uint4 hw;
                hw.x = packh(a.x, c.x);
                hw.y = packh(a.y, c.y);
                hw.z = packh(a.z, c.z);
                hw.w = packh(a.w, c.w);
                *(uint4*)(smu + KHIw + j * 136 + 4 * lane) = hw;
            }
            // V: c = 2j + (lane>>4); s2-words s8..s8+3 (= floats 2*s8..2*s8+7)
#pragma unroll 4
            for (int j = 0; j < 32; j++) {
                const int c  = 2 * j + (lane >> 4);
                const int s8 = (lane & 15) * 4;
                const float* vp = vg + (size_t)c * SEQ + s0 + 2 * s8;
                const float4 v0 = *(const float4*)(vp);
                const float4 v1 = *(const float4*)(vp + 4);
                uint4 hw;
                hw.x = packh(v0.x, v0.y);
                hw.y = packh(v0.z, v0.w);
                hw.z = packh(v1.x, v1.y);
                hw.w = packh(v1.z, v1.w);
                *(uint4*)(smu + VHIw + c * 68 + s8) = hw;
            }
            MBAR_ARRIVE(FULL);   // every lane arrives (count=32), releasing its stores
        }
        return;
    }

    // ================= consumer warps =================
    const int g  = lane >> 2;
    const int q4 = lane & 3;
    const int tb = wid * 16;
    const float CSC = 0.18033688011112042f;   // 0.125 * log2(e)

    // ---- Q prologue: raw fp32 -> scale -> fp16 hi/lo -> smem ----
#pragma unroll
    for (int j = 0; j < 4; j++) {
        int i = tid + j * 256;
        int c2 = i >> 5, t4 = (i & 31) * 4;
        float4 a  = *(const float4*)(qg + (size_t)(2 * c2)     * SEQ + t0 + t4);
        float4 bq = *(const float4*)(qg + (size_t)(2 * c2 + 1) * SEQ + t0 + t4);
        uint4 hw, lw;
        split2h(a.x * CSC, bq.x * CSC, hw.x, lw.x);
        split2h(a.y * CSC, bq.y * CSC, hw.y, lw.y);
        split2h(a.z * CSC, bq.z * CSC, hw.z, lw.z);
        split2h(a.w * CSC, bq.w * CSC, hw.w, lw.w);
        *(uint4*)(smu + QHI_W + c2 * 136 + t4) = hw;
        *(uint4*)(smu + QLO_W + c2 * 136 + t4) = lw;
    }
    BAR_CONS();

    float l0 = 0.f, l1 = 0.f;
    float co[8][4];
#pragma unroll
    for (int nf = 0; nf < 8; nf++)
#pragma unroll
        for (int j = 0; j < 4; j++) co[nf][j] = 0.f;

    for (int st = 0; st < NTILES; ++st) {
        const int buf = st & 1;
        const int KHI = BUF_W + buf * 8704;
        const int VHI = KHI + 4352;
        const uint32_t FULL  = buf ? FULL1  : FULL0;
        const uint32_t EMPTY = buf ? EMPTY1 : EMPTY0;

        mbar_wait(FULL, (uint32_t)((st >> 1) & 1));

        // ---- S = Q^T K : 2-term (Qhi*K + Qlo*K), nf-pair interleaved ----
        float cs[16][4];
#pragma unroll
        for (int nf = 0; nf < 16; nf++)
#pragma unroll
            for (int j = 0; j < 4; j++) cs[nf][j] = 0.f;

#pragma unroll
        for (int kb = 0; kb < 4; kb++) {
            const int r0 = kb * 8 + q4;
            unsigned ahi[4], alo[4];
            ahi[0] = smu[QHI_W + r0 * 136 + tb + g];
            ahi[1] = smu[QHI_W + r0 * 136 + tb + g + 8];
            ahi[2] = smu[QHI_W + (r0 + 4) * 136 + tb + g];
            ahi[3] = smu[QHI_W + (r0 + 4) * 136 + tb + g + 8];
            alo[0] = smu[QLO_W + r0 * 136 + tb + g];
            alo[1] = smu[QLO_W + r0 * 136 + tb + g + 8];
            alo[2] = smu[QLO_W + (r0 + 4) * 136 + tb + g];
            alo[3] = smu[QLO_W + (r0 + 4) * 136 + tb + g + 8];
#pragma unroll
            for (int nfp = 0; nfp < 8; nfp++) {
                const int nf0 = 2 * nfp, nf1 = 2 * nfp + 1;
                const int sc0 = nf0 * 8 + g, sc1 = nf1 * 8 + g;
                unsigned b0h[2], b1h[2];
                b0h[0] = smu[KHI + r0 * 136 + sc0];
                b0h[1] = smu[KHI + (r0 + 4) * 136 + sc0];
                b1h[0] = smu[KHI + r0 * 136 + sc1];
                b1h[1] = smu[KHI + (r0 + 4) * 136 + sc1];
                mma_f16(cs[nf0], ahi, b0h);
                mma_f16(cs[nf1], ahi, b1h);
                mma_f16(cs[nf0], alo, b0h);
                mma_f16(cs[nf1], alo, b1h);
            }
        }

        // ---- softmax numerator: p = exp2(s), no max shift (args bounded) ----
        float rs0 = 0.f, rs1 = 0.f;
#pragma unroll
        for (int nf = 0; nf < 16; nf++) {
            cs[nf][0] = exp2f(cs[nf][0]);
            cs[nf][1] = exp2f(cs[nf][1]);
            cs[nf][2] = exp2f(cs[nf][2]);
            cs[nf][3] = exp2f(cs[nf][3]);
            rs0 += cs[nf][0] + cs[nf][1];
            rs1 += cs[nf][2] + cs[nf][3];
        }
        l0 += rs0;
        l1 += rs1;

        // ---- O += P * V^T (single-term fp16) ----
#pragma unroll
        for (int kb = 0; kb < 8; kb++) {
            unsigned ah[4];
            ah[0] = packh(cs[2 * kb][0],     cs[2 * kb][1]);
            ah[1] = packh(cs[2 * kb][2],     cs[2 * kb][3]);
            ah[2] = packh(cs[2 * kb + 1][0], cs[2 * kb + 1][1]);
            ah[3] = packh(cs[2 * kb + 1][2], cs[2 * kb + 1][3]);
#pragma unroll
            for (int nfp = 0; nfp < 4; nfp++) {
                const int nf0 = 2 * nfp, nf1 = 2 * nfp + 1;
                const int c0 = nf0 * 8 + g, c1 = nf1 * 8 + g;
                unsigned b0h[2], b1h[2];
                b0h[0] = smu[VHI + c0 * 68 + kb * 8 + q4];
                b0h[1] = smu[VHI + c0 * 68 + kb * 8 + 4 + q4];
                b1h[0] = smu[VHI + c1 * 68 + kb * 8 + q4];
                b1h[1] = smu[VHI + c1 * 68 + kb * 8 + 4 + q4];
                mma_f16(co[nf0], ah, b0h);
                mma_f16(co[nf1], ah, b1h);
            }
        }

        MBAR_ARRIVE(EMPTY);
    }

    // ---- finalize rows ----
    l0 += __shfl_xor_sync(0xffffffffu, l0, 1);
    l0 += __shfl_xor_sync(0xffffffffu, l0, 2);
    l1 += __shfl_xor_sync(0xffffffffu, l1, 1);
    l1 += __shfl_xor_sync(0xffffffffu, l1, 2);
    const float inv0 = 1.f / l0;
    const float inv1 = 1.f / l1;
#pragma unroll
    for (int nf = 0; nf < 8; nf++) {
        co[nf][0] *= inv0; co[nf][1] *= inv0;
        co[nf][2] *= inv1; co[nf][3] *= inv1;
    }

    // ---- epilogue: stage O as [c][t] fp32 over Q region ----
    BAR_CONS();
#pragma unroll
    for (int nf = 0; nf < 8; nf++) {
        const int c = nf * 8 + 2 * q4;
        smf[(c)     * OST + tb + g]     = co[nf][0];
        smf[(c + 1) * OST + tb + g]     = co[nf][1];
        smf[(c)     * OST + tb + g + 8] = co[nf][2];
        smf[(c + 1) * OST + tb + g + 8] = co[nf][3];
    }
    BAR_CONS();

#pragma unroll
    for (int j = 0; j < 8; j++) {
        int i = tid + j * 256;
        int c = i >> 5, t4 = (i & 31) * 4;
        *(float4*)(og + (size_t)c * SEQ + t0 + t4) =
            *(const float4*)(smf + c * OST + t4);
    }
}

extern "C" void kernel_launch(void* const* d_in, const int* in_sizes, int n_in,
                              void* d_out, int out_size) {
    (void)in_sizes; (void)n_in; (void)out_size;
    const float* qkv = (const float*)d_in[0];
    float* out = (float*)d_out;

    cudaFuncSetAttribute(qkv_attn_v16,
                         cudaFuncAttributeMaxDynamicSharedMemorySize, SMEM_BYTES);
    dim3 grid(SEQ / BT, 128);
    qkv_attn_v16<<<grid, NTH, SMEM_BYTES>>>(qkv, out);
}

// round 17
// speedup vs baseline: 3.7116x; 3.7116x over previous
#include <cuda_runtime.h>
#include <math.h>
#include <stdint.h>

#define SEQ 1024
#define CH  64
#define BT  128
#define NTILES 8
#define NTH 288          // 8 consumer warps + 1 producer warp

#define ARR (4u * 1024u * 1024u)
__device__ uint32_t g_pre[2ull * ARR];   // KH VH (fp16x2)

// smem word offsets
#define QHI_W 0
#define QLO_W 4352
#define BUF_W 8704            // + buf*8704 : K hi (4352 words), V (+4352); 3 buffers
#define MB_W  34816           // mbarriers: FULL0..2 at +0,+2,+4 ; EMPTY0..2 at +6,+8,+10
#define SMEM_WORDS 34828
#define SMEM_BYTES (SMEM_WORDS * 4)   // 139312
#define OST 132

__device__ __forceinline__ void split2h(float f0, float f1, unsigned& hi, unsigned& lo) {
    unsigned h;
    asm("cvt.rn.f16x2.f32 %0, %1, %2;" : "=r"(h) : "f"(f1), "f"(f0));
    float h0, h1;
    asm("{ .reg .b16 a,b; mov.b32 {a,b}, %2; cvt.f32.f16 %0, a; cvt.f32.f16 %1, b; }"
        : "=f"(h0), "=f"(h1) : "r"(h));
    float r0 = f0 - h0, r1 = f1 - h1;
    asm("cvt.rn.f16x2.f32 %0, %1, %2;" : "=r"(lo) : "f"(r1), "f"(r0));
    hi = h;
}
__device__ __forceinline__ unsigned packh(float f0, float f1) {
    unsigned h;
    asm("cvt.rn.f16x2.f32 %0, %1, %2;" : "=r"(h) : "f"(f1), "f"(f0));
    return h;
}
__device__ __forceinline__ void mma_f16(float* d, const unsigned* a, const unsigned* b) {
    asm volatile(
        "mma.sync.aligned.m16n8k16.row.col.f32.f16.f16.f32 "
        "{%0,%1,%2,%3}, {%4,%5,%6,%7}, {%8,%9}, {%0,%1,%2,%3};\n"
        : "+f"(d[0]), "+f"(d[1]), "+f"(d[2]), "+f"(d[3])
        : "r"(a[0]), "r"(a[1]), "r"(a[2]), "r"(a[3]), "r"(b[0]), "r"(b[1]));
}
__device__ __forceinline__ uint32_t smem_u32(const void* p) {
    uint32_t a;
    asm("{ .reg .u64 t; cvta.to.shared.u64 t, %1; cvt.u32.u64 %0, t; }" : "=r"(a) : "l"(p));
    return a;
}
__device__ __forceinline__ void cpa(uint32_t dst, const uint32_t* src) {
    asm volatile("cp.async.cg.shared.global [%0], [%1], 16;" :: "r"(dst), "l"(src));
}
#define CP_MBAR_ARRIVE(mb) \
    asm volatile("cp.async.mbarrier.arrive.noinc.shared.b64 [%0];" :: "r"(mb) : "memory")
#define MBAR_INIT(mb, cnt) \
    asm volatile("mbarrier.init.shared.b64 [%0], %1;" :: "r"(mb), "r"((uint32_t)(cnt)) : "memory")
#define MBAR_ARRIVE(mb) \
    asm volatile("mbarrier.arrive.shared.b64 _, [%0];" :: "r"(mb) : "memory")
#define BAR_CONS() asm volatile("bar.sync 1, 256;" ::: "memory")

__device__ __forceinline__ void mbar_wait(uint32_t mb, uint32_t parity) {
    uint32_t done;
    asm volatile("{\n\t.reg .pred p;\n\t"
        "mbarrier.try_wait.parity.shared.b64 p, [%1], %2;\n\t"
        "selp.b32 %0, 1, 0, p;\n\t}" : "=r"(done) : "r"(mb), "r"(parity) : "memory");
    while (!done) {
        asm volatile("{\n\t.reg .pred p;\n\t"
            "mbarrier.try_wait.parity.shared.b64 p, [%1], %2;\n\t"
            "selp.b32 %0, 1, 0, p;\n\t}" : "=r"(done) : "r"(mb), "r"(parity) : "memory");
    }
}

// ============ prepass: fp32 K,V -> KH VH (fp16x2) ============
__global__ __launch_bounds__(256)
void prepass(const float* __restrict__ qkv) {
    const int hb = blockIdx.y;
    const int b = hb >> 4, h = hb & 15;
    const int sq = blockIdx.x * 256;

    const float* kg = qkv + ((size_t)b * 3072 + 1024 + (size_t)h * CH) * SEQ;
    const float* vg = kg + (size_t)1024 * SEQ;

    uint32_t* KH = g_pre + 0 * (size_t)ARR + (size_t)hb * 32768;
    uint32_t* VH = g_pre + 1 * (size_t)ARR + (size_t)hb * 32768;

    const int tid = threadIdx.x;

    for (int i = tid; i < 2048; i += 256) {
        int c2 = i >> 6, s4 = sq + (i & 63) * 4;
        float4 ka = *(const float4*)(kg + (size_t)(2 * c2)     * SEQ + s4);
        float4 kb = *(const float4*)(kg + (size_t)(2 * c2 + 1) * SEQ + s4);
        uint4 hw;
        hw.x = packh(ka.x, kb.x);
        hw.y = packh(ka.y, kb.y);
        hw.z = packh(ka.z, kb.z);
        hw.w = packh(ka.w, kb.w);
        *(uint4*)(KH + c2 * 1024 + s4) = hw;
    }
    for (int i = tid; i < 4096; i += 256) {
        int c = i >> 6, s4 = sq + (i & 63) * 4;
        float4 v = *(const float4*)(vg + (size_t)c * SEQ + s4);
        uint2 hw;
        hw.x = packh(v.x, v.y);
        hw.y = packh(v.z, v.w);
        *(uint2*)(VH + c * 512 + (s4 >> 1)) = hw;
    }
}

// ============ attention: producer warp + 8 consumer warps, 3 buffers ============
__global__ __launch_bounds__(NTH, 1)
void qkv_attn_v17(const float* __restrict__ qkv, float* __restrict__ out) {
    extern __shared__ unsigned smu[];
    float* smf = (float*)smu;

    const int t0 = blockIdx.x * BT;
    const int hb = blockIdx.y;
    const int b  = hb >> 4;
    const int h  = hb & 15;

    const float*    qg  = qkv + ((size_t)b * 3072 + (size_t)h * CH) * SEQ;
    const uint32_t* KHg = g_pre + 0 * (size_t)ARR + (size_t)hb * 32768;
    const uint32_t* VHg = g_pre + 1 * (size_t)ARR + (size_t)hb * 32768;

    float* og = out + ((size_t)b * 1024 + (size_t)h * CH) * SEQ;

    const int tid  = threadIdx.x;
    const int wid  = tid >> 5;
    const int lane = tid & 31;
    const uint32_t smb = smem_u32(smu);

    if (tid == 0) {
#pragma unroll
        for (int i = 0; i < 3; i++) {
            MBAR_INIT(smb + (MB_W + 2 * i) * 4, 32);        // FULL i
            MBAR_INIT(smb + (MB_W + 6 + 2 * i) * 4, 256);   // EMPTY i
        }
    }
    __syncthreads();

    if (wid == 8) {
        // ================= producer warp =================
#pragma unroll
        for (int st = 0; st < NTILES; st++) {
            const int k3  = st / 3;
            const int buf = st - 3 * k3;
            const uint32_t FULL  = smb + (MB_W + 2 * buf) * 4;
            const uint32_t EMPTY = smb + (MB_W + 6 + 2 * buf) * 4;
            if (st >= 3) mbar_wait(EMPTY, (uint32_t)((k3 - 1) & 1));
            const int s0 = st * 128;
            const uint32_t kdst = smb + (uint32_t)(BUF_W + buf * 8704) * 4;
            const uint32_t vdst = kdst + 4352u * 4;
#pragma unroll
            for (int j = 0; j < 32; j++) {
                int idx = lane + j * 32; int r = idx >> 5, o = (idx & 31) * 4;
                cpa(kdst + (uint32_t)(r * 136 + o) * 4, KHg + r * 1024 + s0 + o);
            }
#pragma unroll
            for (int j = 0; j < 32; j++) {
                int idx = lane + j * 32; int r = idx >> 4, o = (idx & 15) * 4;
                cpa(vdst + (uint32_t)(r * 68 + o) * 4, VHg + r * 512 + (s0 >> 1) + o);
            }
            CP_MBAR_ARRIVE(FULL);
        }
        return;
    }

    // ================= consumer warps =================
    const int g  = lane >> 2;
    const int q4 = lane & 3;
    const int tb = wid * 16;
    const float CSC = 0.18033688011112042f;   // 0.125 * log2(e)

    // ---- Q prologue: raw fp32 -> scale -> fp16 hi/lo -> smem ----
#pragma unroll
    for (int j = 0; j < 4; j++) {
        int i = tid + j * 256;
        int c2 = i >> 5, t4 = (i & 31) * 4;
        float4 a  = *(const float4*)(qg + (size_t)(2 * c2)     * SEQ + t0 + t4);
        float4 bq = *(const float4*)(qg + (size_t)(2 * c2 + 1) * SEQ + t0 + t4);
        uint4 hw, lw;
        split2h(a.x * CSC, bq.x * CSC, hw.x, lw.x);
        split2h(a.y * CSC, bq.y * CSC, hw.y, lw.y);
        split2h(a.z * CSC, bq.z * CSC, hw.z, lw.z);
        split2h(a.w * CSC, bq.w * CSC, hw.w, lw.w);
        *(uint4*)(smu + QHI_W + c2 * 136 + t4) = hw;
        *(uint4*)(smu + QLO_W + c2 * 136 + t4) = lw;
    }
    BAR_CONS();

    float l0 = 0.f, l1 = 0.f;
    float co[8][4];
#pragma unroll
    for (int nf = 0; nf < 8; nf++)
#pragma unroll
        for (int j = 0; j < 4; j++) co[nf][j] = 0.f;

    for (int st = 0; st < NTILES; ++st) {
        const int k3  = st / 3;
        const int buf = st - 3 * k3;
        const int KHI = BUF_W + buf * 8704;
        const int VHI = KHI + 4352;
        const uint32_t FULL  = smb + (MB_W + 2 * buf) * 4;
        const uint32_t EMPTY = smb + (MB_W + 6 + 2 * buf) * 4;

        mbar_wait(FULL, (uint32_t)(k3 & 1));

        // ---- S = Q^T K : 2-term (Qhi*K + Qlo*K), nf-pair interleaved ----
        float cs[16][4];
#pragma unroll
        for (int nf = 0; nf < 16; nf++)
#pragma unroll
            for (int j = 0; j < 4; j++) cs[nf][j] = 0.f;

#pragma unroll
        for (int kb = 0; kb < 4; kb++) {
            const int r0 = kb * 8 + q4;
            unsigned ahi[4], alo[4];
            ahi[0] = smu[QHI_W + r0 * 136 + tb + g];
            ahi[1] = smu[QHI_W + r0 * 136 + tb + g + 8];
            ahi[2] = smu[QHI_W + (r0 + 4) * 136 + tb + g];
            ahi[3] = smu[QHI_W + (r0 + 4) * 136 + tb + g + 8];
            alo[0] = smu[QLO_W + r0 * 136 + tb + g];
            alo[1] = smu[QLO_W + r0 * 136 + tb + g + 8];
            alo[2] = smu[QLO_W + (r0 + 4) * 136 + tb + g];
            alo[3] = smu[QLO_W + (r0 + 4) * 136 + tb + g + 8];
#pragma unroll
            for (int nfp = 0; nfp < 8; nfp++) {
                const int nf0 = 2 * nfp, nf1 = 2 * nfp + 1;
                const int sc0 = nf0 * 8 + g, sc1 = nf1 * 8 + g;
                unsigned b0h[2], b1h[2];
                b0h[0] = smu[KHI + r0 * 136 + sc0];
                b0h[1] = smu[KHI + (r0 + 4) * 136 + sc0];
                b1h[0] = smu[KHI + r0 * 136 + sc1];
                b1h[1] = smu[KHI + (r0 + 4) * 136 + sc1];
                mma_f16(cs[nf0], ahi, b0h);
                mma_f16(cs[nf1], ahi, b1h);
                mma_f16(cs[nf0], alo, b0h);
                mma_f16(cs[nf1], alo, b1h);
            }
        }

        // ---- fused softmax + O-GEMM: per-kb exp2 -> pack -> MMA ----
        float rs0 = 0.f, rs1 = 0.f;
#pragma unroll
        for (int kb = 0; kb < 8; kb++) {
            float e0 = exp2f(cs[2 * kb][0]);
            float e1 = exp2f(cs[2 * kb][1]);
            float e2 = exp2f(cs[2 * kb][2]);
            float e3 = exp2f(cs[2 * kb][3]);
            float e4 = exp2f(cs[2 * kb + 1][0]);
            float e5 = exp2f(cs[2 * kb + 1][1]);
            float e6 = exp2f(cs[2 * kb + 1][2]);
            float e7 = exp2f(cs[2 * kb + 1][3]);
            rs0 += (e0 + e1) + (e4 + e5);
            rs1 += (e2 + e3) + (e6 + e7);
            unsigned ah[4];
            ah[0] = packh(e0, e1);
            ah[1] = packh(e2, e3);
            ah[2] = packh(e4, e5);
            ah[3] = packh(e6, e7);
#pragma unroll
            for (int nfp = 0; nfp < 4; nfp++) {
                const int nf0 = 2 * nfp, nf1 = 2 * nfp + 1;
                const int c0 = nf0 * 8 + g, c1 = nf1 * 8 + g;
                unsigned b0h[2], b1h[2];
                b0h[0] = smu[VHI + c0 * 68 + kb * 8 + q4];
                b0h[1] = smu[VHI + c0 * 68 + kb * 8 + 4 + q4];
                b1h[0] = smu[VHI + c1 * 68 + kb * 8 + q4];
                b1h[1] = smu[VHI + c1 * 68 + kb * 8 + 4 + q4];
                mma_f16(co[nf0], ah, b0h);
                mma_f16(co[nf1], ah, b1h);
            }
        }
        l0 += rs0;
        l1 += rs1;

        MBAR_ARRIVE(EMPTY);
    }

    // ---- finalize rows ----
    l0 += __shfl_xor_sync(0xffffffffu, l0, 1);
    l0 += __shfl_xor_sync(0xffffffffu, l0, 2);
    l1 += __shfl_xor_sync(0xffffffffu, l1, 1);
    l1 += __shfl_xor_sync(0xffffffffu, l1, 2);
    const float inv0 = 1.f / l0;
    const float inv1 = 1.f / l1;
#pragma unroll
    for (int nf = 0; nf < 8; nf++) {
        co[nf][0] *= inv0; co[nf][1] *= inv0;
        co[nf][2] *= inv1; co[nf][3] *= inv1;
    }

    // ---- epilogue: stage O as [c][t] fp32 over Q region ----
    BAR_CONS();
#pragma unroll
    for (int nf = 0; nf < 8; nf++) {
        const int c = nf * 8 + 2 * q4;
        smf[(c)     * OST + tb + g]     = co[nf][0];
        smf[(c + 1) * OST + tb + g]     = co[nf][1];
        smf[(c)     * OST + tb + g + 8] = co[nf][2];
        smf[(c + 1) * OST + tb + g + 8] = co[nf][3];
    }
    BAR_CONS();

#pragma unroll
    for (int j = 0; j < 8; j++) {
        int i = tid + j * 256;
        int c = i >> 5, t4 = (i & 31) * 4;
        *(float4*)(og + (size_t)c * SEQ + t0 + t4) =
            *(const float4*)(smf + c * OST + t4);
    }
}

extern "C" void kernel_launch(void* const* d_in, const int* in_sizes, int n_in,
                              void* d_out, int out_size) {
    (void)in_sizes; (void)n_in; (void)out_size;
    const float* qkv = (const float*)d_in[0];
    float* out = (float*)d_out;

    prepass<<<dim3(4, 128), 256>>>(qkv);

    cudaFuncSetAttribute(qkv_attn_v17,
                         cudaFuncAttributeMaxDynamicSharedMemorySize, SMEM_BYTES);
    dim3 grid(SEQ / BT, 128);
    qkv_attn_v17<<<grid, NTH, SMEM_BYTES>>>(qkv, out);
}